// round 7
// baseline (speedup 1.0000x reference)
#include <cuda_runtime.h>
#include <cstdint>

#define L2E 1.4426950408889634f
#define BATCH 64
#define SEQ 512
#define HID 768
#define NC 21
#define EM_STRIDE (SEQ * NC)   // 10752 floats per batch

__device__ __align__(16) float g_em2[BATCH * SEQ * NC];  // log2-scaled emissions
__device__ __align__(16) float g_emx[BATCH * SEQ * NC];  // 2^em2 (linear)
__device__ float g_res[BATCH];                           // per-batch (logZ2 - num2)

__device__ __forceinline__ float fast_ex2(float x) {
    float y; asm("ex2.approx.ftz.f32 %0, %1;" : "=f"(y) : "f"(x)); return y;
}
__device__ __forceinline__ float fast_lg2(float x) {
    float y; asm("lg2.approx.ftz.f32 %0, %1;" : "=f"(y) : "f"(x)); return y;
}
__device__ __forceinline__ void cp_async4(void* smem_dst, const void* gmem_src) {
    unsigned d = (unsigned)__cvta_generic_to_shared(smem_dst);
    asm volatile("cp.async.ca.shared.global [%0], [%1], 4;" :: "r"(d), "l"(gmem_src));
}
__device__ __forceinline__ void cp_commit() {
    asm volatile("cp.async.commit_group;");
}
#define FFMA2(acc, a, b) \
    asm("fma.rn.f32x2 %0, %1, %2, %3;" : "=l"(acc) : "l"(a), "l"(b), "l"(acc))

// ---------------------------------------------------------------------------
// Kernel 1: emissions GEMM. R7: 3-stage cp.async pipeline with ONE barrier
// per k-iter (was 2-stage / 2 barriers -> barrier+drain stalls dominated).
// The K-split merge region ALIASES the pipeline smem (used strictly after
// the final barrier) to fit 3 stages in 48KB static smem.
// 512 blocks x 256 threads, BM=64, BK=32.
// thread = (m2 = tid&31 -> rows {m2, m2+32}, half = (tid>>5)&1 -> 12 cols,
//           ks = tid>>6 -> 8 of 32 kk). 4-way K-split merged via smem.
// ---------------------------------------------------------------------------
#define HS_BYTES (3 * 64 * 33 * 4)   // 25344
#define WS_BYTES (3 * 32 * 24 * 4)   // 9216

__global__ __launch_bounds__(256) void gemm_kernel(
    const float* __restrict__ hidden,
    const float* __restrict__ W,
    const float* __restrict__ bias)
{
    __shared__ __align__(16) char raw[HS_BYTES + WS_BYTES];   // 34560 B
    float (*hs)[64][33]   = reinterpret_cast<float(*)[64][33]>(raw);
    float (*ws)[32][24]   = reinterpret_cast<float(*)[32][24]>(raw + HS_BYTES);
    uint64_t (*mrg)[3][12] = reinterpret_cast<uint64_t(*)[3][12]>(raw); // alias

    const int tid  = threadIdx.x;
    const int m2   = tid & 31;
    const int half = (tid >> 5) & 1;
    const int ks   = tid >> 6;           // 0..3
    const int grp  = tid & 63;
    const int row0 = blockIdx.x * 64;

    // zero ws pad columns (cols 21..23; cp.async never writes them, and each
    // stage buffer is reused with pads intact). First read is after barrier.
    if (tid < 192) {  // 2 pads per thread covers 3*32*3 = 288
        int i0 = tid, i1 = tid + 192;
        { int s = i0 / 96, rem = i0 % 96; ws[s][rem / 3][21 + rem % 3] = 0.f; }
        if (i1 < 288) { int s = i1 / 96, rem = i1 % 96; ws[s][rem / 3][21 + rem % 3] = 0.f; }
    }

    auto issue = [&](int k0, int s) {
#pragma unroll
        for (int u = 0; u < 8; u++) {                 // 2048 floats / 256 thr
            int idx = tid + u * 256;
            int r = idx >> 5, kk = idx & 31;
            cp_async4(&hs[s][r][kk], &hidden[(row0 + r) * HID + k0 + kk]);
        }
#pragma unroll
        for (int u = 0; u < 3; u++) {                 // 672 floats
            int idx = tid + u * 256;
            if (idx < 32 * NC) {
                int kk = idx / NC, c = idx - kk * NC;
                cp_async4(&ws[s][kk][c], &W[(k0 + kk) * NC + c]);
            }
        }
    };

    uint64_t acc[2][6];
#pragma unroll
    for (int r = 0; r < 2; r++)
#pragma unroll
        for (int i = 0; i < 6; i++) acc[r][i] = 0ull;

    issue(0, 0);  cp_commit();
    issue(32, 1); cp_commit();

    const int NK = HID / 32;   // 24
    const int kklo = ks * 8;
    for (int k = 0; k < NK; k++) {
        // my stage-k copies done (<=1 newer group pending), then barrier
        // publishes everyone's; barrier also proves all warps finished the
        // iter k-1 compute that read buffer (k+2)%3 == (k-1)%3.
        if (k < NK - 1) asm volatile("cp.async.wait_group 1;");
        else            asm volatile("cp.async.wait_group 0;");
        __syncthreads();
        if (k + 2 < NK) { issue((k + 2) * 32, (k + 2) % 3); cp_commit(); }

        const int s = k % 3;
#pragma unroll
        for (int kk = kklo; kk < kklo + 8; kk++) {
            float h0 = hs[s][m2][kk];
            float h1 = hs[s][m2 + 32][kk];
            uint64_t h0x, h1x;
            asm("mov.b64 %0, {%1, %1};" : "=l"(h0x) : "f"(h0));
            asm("mov.b64 %0, {%1, %1};" : "=l"(h1x) : "f"(h1));
            const ulonglong2* wp =
                reinterpret_cast<const ulonglong2*>(&ws[s][kk][half * 12]);
            ulonglong2 q0 = wp[0], q1 = wp[1], q2 = wp[2];
            FFMA2(acc[0][0], h0x, q0.x); FFMA2(acc[0][1], h0x, q0.y);
            FFMA2(acc[0][2], h0x, q1.x); FFMA2(acc[0][3], h0x, q1.y);
            FFMA2(acc[0][4], h0x, q2.x); FFMA2(acc[0][5], h0x, q2.y);
            FFMA2(acc[1][0], h1x, q0.x); FFMA2(acc[1][1], h1x, q0.y);
            FFMA2(acc[1][2], h1x, q1.x); FFMA2(acc[1][3], h1x, q1.y);
            FFMA2(acc[1][4], h1x, q2.x); FFMA2(acc[1][5], h1x, q2.y);
        }
    }
    __syncthreads();   // all compute reads done before merge aliases raw[]

    // merge 4-way K-split partials, apply bias, write em2 + emx
    if (ks != 0) {
#pragma unroll
        for (int r = 0; r < 2; r++)
#pragma unroll
            for (int i = 0; i < 6; i++) mrg[grp][ks - 1][r * 6 + i] = acc[r][i];
    }
    __syncthreads();
    if (ks == 0) {
        const int cb = half * 12;
#pragma unroll
        for (int r = 0; r < 2; r++) {
            const int out_base = (row0 + m2 + r * 32) * NC;
#pragma unroll
            for (int p = 0; p < 6; p++) {
                uint64_t sum = acc[r][p];
#pragma unroll
                for (int q = 0; q < 3; q++) {
                    uint64_t o = mrg[grp][q][r * 6 + p];
                    asm("add.rn.f32x2 %0, %1, %2;" : "=l"(sum) : "l"(sum), "l"(o));
                }
                float2 f = *reinterpret_cast<float2*>(&sum);
                int c = cb + 2 * p;
                if (c < NC) {
                    float v = (f.x + bias[c]) * L2E;
                    g_em2[out_base + c] = v;
                    g_emx[out_base + c] = fast_ex2(v);
                }
                if (c + 1 < NC) {
                    float v = (f.y + bias[c + 1]) * L2E;
                    g_em2[out_base + c + 1] = v;
                    g_emx[out_base + c + 1] = fast_ex2(v);
                }
            }
        }
    }
}

// ---------------------------------------------------------------------------
// Kernel 2: per-batch CRF, linear-space scan, smem-broadcast alpha.
// R7: explicit x2 unroll over t with fixed ping-pong buffers (less loop
// overhead on the serial chain).
// ---------------------------------------------------------------------------
__global__ __launch_bounds__(128) void crf_kernel(
    const float* __restrict__ start_t,
    const float* __restrict__ end_t,
    const float* __restrict__ trans,
    const int*   __restrict__ labr)
{
    __shared__ __align__(16) float emx_s[SEQ * NC];  // 43008 B
    __shared__ __align__(16) float av[2][24];
    __shared__ float red_f[128];
    __shared__ int   red_i[128];
    __shared__ float s_num2;
    __shared__ int   s_len;

    const int b   = blockIdx.x;
    const int tid = threadIdx.x;
    const float* em_g  = g_em2 + b * EM_STRIDE;
    const float* emx_g = g_emx + b * EM_STRIDE;

    // labels dtype detection (int32 vs int64; reads in-bounds for both)
    int ok = 1;
    for (int t = tid; t < SEQ; t += 128) {
        int v = labr[2 * t + 1];
        if (v != 0 && v != -1) ok = 0;
    }
    int is64 = __syncthreads_and(ok);
    const int lbase = is64 ? b * SEQ * 2 : b * SEQ;
    const int lstep = is64 ? 2 : 1;
#define LAB(t) labr[lbase + (t) * lstep]

    for (int i = tid; i < (SEQ * NC) / 4; i += 128)
        reinterpret_cast<float4*>(emx_s)[i] =
            reinterpret_cast<const float4*>(emx_g)[i];

    // numerator (log2 domain) + valid length (mask is a prefix)
    float p = 0.f;
    int cnt = 0;
    for (int t = tid; t < SEQ; t += 128) {
        int l = LAB(t);
        if (l != -100) {
            cnt++;
            if (t == 0) {
                p += start_t[l] * L2E + em_g[l];
            } else {
                int lp = LAB(t - 1);
                p += em_g[t * NC + l] + trans[lp * NC + l] * L2E;
            }
        }
    }
    red_f[tid] = p;
    red_i[tid] = cnt;
    __syncthreads();
    for (int s = 64; s > 0; s >>= 1) {
        if (tid < s) { red_f[tid] += red_f[tid + s]; red_i[tid] += red_i[tid + s]; }
        __syncthreads();
    }
    if (tid == 0) {
        int len = red_i[0];
        s_len   = len;
        s_num2  = red_f[0] + end_t[LAB(len - 1)] * L2E;
    }
    __syncthreads();

    if (tid < 32) {
        const int lane = tid;
        const int j = lane < NC ? lane : NC - 1;
        float tl[24];
#pragma unroll
        for (int i = 0; i < NC; i++) tl[i] = fast_ex2(trans[i * NC + j] * L2E);
        tl[21] = tl[22] = tl[23] = 0.f;
        const float endx = fast_ex2(end_t[j] * L2E);

        float a = fast_ex2(start_t[j] * L2E) * emx_s[j];
        if (lane < NC)  av[0][lane] = a;
        if (lane >= NC && lane < 24) { av[0][lane] = 0.f; av[1][lane] = 0.f; }
        int offe = 0;
        const int len = s_len;

        auto step = [&](const float* __restrict__ src,
                        float* __restrict__ dst, int t) {
            __syncwarp();
            const float4* vp = reinterpret_cast<const float4*>(src);
            float4 v0 = vp[0], v1 = vp[1], v2 = vp[2],
                   v3 = vp[3], v4 = vp[4], v5 = vp[5];
            float emn = emx_s[t * NC + j];
            int   e     = ((__float_as_int(v0.x) >> 23) & 255) - 127;
            float sclem = __int_as_float((127 - e) << 23) * emn;  // exact 2^-e
            offe += e;

            float s0 = v0.x * tl[0],  s1 = v0.y * tl[1],  s2 = v0.z * tl[2];
            float s3 = v0.w * tl[3],  s4 = v1.x * tl[4],  s5 = v1.y * tl[5];
            s0 += v1.z * tl[6];   s1 += v1.w * tl[7];   s2 += v2.x * tl[8];
            s3 += v2.y * tl[9];   s4 += v2.z * tl[10];  s5 += v2.w * tl[11];
            s0 += v3.x * tl[12];  s1 += v3.y * tl[13];  s2 += v3.z * tl[14];
            s3 += v3.w * tl[15];  s4 += v4.x * tl[16];  s5 += v4.y * tl[17];
            s0 += v4.z * tl[18];  s1 += v4.w * tl[19];  s2 += v5.x * tl[20];
            s3 += v5.y * tl[21];  s4 += v5.z * tl[22];  s5 += v5.w * tl[23];

            a = (((s0 + s1) + (s2 + s3)) + (s4 + s5)) * sclem;
            if (lane < NC) dst[lane] = a;
        };

        int t = 1;
        for (; t + 1 < len; t += 2) {
            step(av[0], av[1], t);
            step(av[1], av[0], t + 1);
        }
        if (t < len) step(av[0], av[1], t);
        __syncwarp();

        float ex = (lane < NC) ? a * endx : 0.f;
#pragma unroll
        for (int d = 16; d > 0; d >>= 1)
            ex += __shfl_xor_sync(0xffffffffu, ex, d);
        if (lane == 0)
            g_res[b] = (float)offe + fast_lg2(ex) - s_num2;
    }
#undef LAB
}

// ---------------------------------------------------------------------------
__global__ void finish_kernel(float* __restrict__ out) {
    int tid = threadIdx.x;           // 32 threads
    float v = g_res[tid] + g_res[tid + 32];
#pragma unroll
    for (int d = 16; d > 0; d >>= 1)
        v += __shfl_xor_sync(0xffffffffu, v, d);
    if (tid == 0) out[0] = v * (1.0f / (64.0f * L2E));
}

// ---------------------------------------------------------------------------
extern "C" void kernel_launch(void* const* d_in, const int* in_sizes, int n_in,
                              void* d_out, int out_size)
{
    const float* hidden = nullptr;
    const float* W      = nullptr;
    const float* trans  = nullptr;
    const int*   labels = nullptr;
    const float* small[3] = {nullptr, nullptr, nullptr};
    int nsmall = 0;

    for (int i = 0; i < n_in; i++) {
        switch (in_sizes[i]) {
            case BATCH * SEQ * HID: hidden = (const float*)d_in[i]; break;
            case HID * NC:          W      = (const float*)d_in[i]; break;
            case NC * NC:           trans  = (const float*)d_in[i]; break;
            case BATCH * SEQ:       labels = (const int*)d_in[i];   break;
            case NC: if (nsmall < 3) small[nsmall++] = (const float*)d_in[i]; break;
            default: break;
        }
    }
    const float* bias    = small[0];
    const float* start_t = small[1];
    const float* end_t   = small[2];

    gemm_kernel<<<512, 256>>>(hidden, W, bias);
    crf_kernel<<<BATCH, 128>>>(start_t, end_t, trans, labels);
    finish_kernel<<<1, 32>>>((float*)d_out);
}